// round 14
// baseline (speedup 1.0000x reference)
#include <cuda_runtime.h>

// LIF activation recurrence (single chunk per lane, deep batched prefetch):
//   keep = (Vm < 1) ? Vm : 0
//   Vm   = relu(x_t + (1 - w_leak) * keep)
//   out  = (Vm > 1) ? 1 : 0
// x: [B=128, T=1000, C=512] f32, w_leak: [C] f32, out: [B, T, C] f32.
//
// One thread per (b,c) lane: 65536 threads = 2048 warps (~13.8/SM), fully
// coalesced 128B/warp per timestep. U=25 double-buffered BATCHED prefetch:
// the 25-deep LDG bursts force ptxas to keep all buffer registers live
// (R9 showed 1:1 interleaving lets it collapse MLP to ~10), giving ~44KB
// of reads in flight per SM. T-splitting was reverted: it improves ncu
// kernel time but costs ~6us at bench replay (R10/R13 both Delta~11.7us
// vs single-chunk Delta~6us).

#define LIF_B 128
#define LIF_T 1000
#define LIF_C 512
#define LIF_U 25                 // 1000 = 25 (prime) + 19*50 (loop) + 50 (tail)
#define LIF_BLOCK 64

__device__ __forceinline__ float lif_step(float& vm, float wl, float xv) {
    float vk = (vm < 1.0f) ? vm : 0.0f;                       // hard-reset gate
    vm = fmaxf(__fadd_rn(xv, __fmul_rn(wl, vk)), 0.0f);       // relu, unfused mul+add
    return (vm > 1.0f) ? 1.0f : 0.0f;                         // spike
}

__global__ __launch_bounds__(LIF_BLOCK)
void lif_kernel(const float* __restrict__ x,
                const float* __restrict__ w_leak,
                float* __restrict__ out) {
    const int i = blockIdx.x * LIF_BLOCK + threadIdx.x;  // 0 .. B*C-1
    const int c = i & (LIF_C - 1);
    const int b = i >> 9;                                // log2(C) = 9

    const float wl = 1.0f - w_leak[c];
    const size_t base = (size_t)b * LIF_T * LIF_C + c;
    const float* xp = x + base;
    float*       op = out + base;

    float vm = 0.0f;

    // Two fixed-name register buffers (no dynamic indexing -> no spill).
    float bufA[LIF_U], bufB[LIF_U];

    // Prime buffer A with t = 0..24
    #pragma unroll
    for (int u = 0; u < LIF_U; u++)
        bufA[u] = __ldcs(xp + (size_t)u * LIF_C);

    // Main loop: 19 iterations x 50 timesteps, t = 0,50,...,900.
    // Last iteration prefetches A from t=950..974 -- in bounds.
    #pragma unroll 1
    for (int t = 0; t <= LIF_T - 4 * LIF_U; t += 2 * LIF_U) {
        // prefetch t+25 .. t+49 into B (batched: keeps 25 LDGs in flight)
        #pragma unroll
        for (int u = 0; u < LIF_U; u++)
            bufB[u] = __ldcs(xp + (size_t)(t + LIF_U + u) * LIF_C);

        // compute t .. t+24 from A
        #pragma unroll
        for (int u = 0; u < LIF_U; u++)
            __stcs(op + (size_t)(t + u) * LIF_C, lif_step(vm, wl, bufA[u]));

        // prefetch t+50 .. t+74 into A
        #pragma unroll
        for (int u = 0; u < LIF_U; u++)
            bufA[u] = __ldcs(xp + (size_t)(t + 2 * LIF_U + u) * LIF_C);

        // compute t+25 .. t+49 from B
        #pragma unroll
        for (int u = 0; u < LIF_U; u++)
            __stcs(op + (size_t)(t + LIF_U + u) * LIF_C, lif_step(vm, wl, bufB[u]));
    }

    // Tail: computed through t=949; bufA holds 950..974. Load 975..999, finish.
    #pragma unroll
    for (int u = 0; u < LIF_U; u++)
        bufB[u] = __ldcs(xp + (size_t)(LIF_T - LIF_U + u) * LIF_C);

    #pragma unroll
    for (int u = 0; u < LIF_U; u++)
        __stcs(op + (size_t)(LIF_T - 2 * LIF_U + u) * LIF_C, lif_step(vm, wl, bufA[u]));

    #pragma unroll
    for (int u = 0; u < LIF_U; u++)
        __stcs(op + (size_t)(LIF_T - LIF_U + u) * LIF_C, lif_step(vm, wl, bufB[u]));
}

extern "C" void kernel_launch(void* const* d_in, const int* in_sizes, int n_in,
                              void* d_out, int out_size) {
    const float* x      = (const float*)d_in[0];   // [B, T, C] f32
    const float* w_leak = (const float*)d_in[1];   // [C] f32
    float* out = (float*)d_out;                    // [B, T, C] f32

    const int total = LIF_B * LIF_C;               // 65536 lanes
    lif_kernel<<<total / LIF_BLOCK, LIF_BLOCK>>>(x, w_leak, out);
}